// round 6
// baseline (speedup 1.0000x reference)
#include <cuda_runtime.h>
#include <cstdint>
#include <stdint.h>
#include <math.h>

#define FULL 0xffffffffu
#define LOG2E 1.4426950408889634f
#define LN2   0.6931471805599453f

// Precomputed log_softmax(W_m, axis=0) * LOG2E  [32,32,32] (16B-aligned for cp.async)
// g_a0b: a0 in log2 units, blocked lane layout: lane i holds k' = 4(i%8)+(i>>3)
__device__ __align__(16) float g_wl2[32 * 32 * 32];
__device__ float g_a0b[32];

__device__ __forceinline__ float ex2f(float x) {
    float y; asm("ex2.approx.f32 %0, %1;" : "=f"(y) : "f"(x)); return y;
}
__device__ __forceinline__ float lg2f(float x) {
    float y; asm("lg2.approx.f32 %0, %1;" : "=f"(y) : "f"(x)); return y;
}
__device__ __forceinline__ void cpa16(unsigned int dst, const float4* src) {
    asm volatile("cp.async.cg.shared.global [%0], [%1], 16;" :: "r"(dst), "l"(src));
}
#define CP_COMMIT() asm volatile("cp.async.commit_group;" ::: "memory")
#define CP_WAIT1()  asm volatile("cp.async.wait_group 1;" ::: "memory")

// ---------------------------------------------------------------------------
// Prep: thread t = (m, k') computes log_softmax over k of W[m, k, k'] (axis=0),
// scaled by LOG2E. Threads 0..31 also compute a0 (log2 units, blocked layout).
// ---------------------------------------------------------------------------
__global__ void tt_prep_kernel(const float* __restrict__ W,
                               const float* __restrict__ wk0) {
    int t = threadIdx.x;
    int m = t >> 5, kp = t & 31;

    float v[32];
    float mx = -INFINITY;
#pragma unroll
    for (int k = 0; k < 32; k++) {
        v[k] = W[m * 1024 + k * 32 + kp];
        mx = fmaxf(mx, v[k]);
    }
    float s = 0.f;
#pragma unroll
    for (int k = 0; k < 32; k++) s += expf(v[k] - mx);
    float lse = mx + logf(s);
#pragma unroll
    for (int k = 0; k < 32; k++)
        g_wl2[m * 1024 + k * 32 + kp] = (v[k] - lse) * LOG2E;

    if (t < 32) {
        float m2 = -INFINITY;
#pragma unroll
        for (int k = 0; k < 32; k++) m2 = fmaxf(m2, wk0[k]);
        float s2 = 0.f;
#pragma unroll
        for (int k = 0; k < 32; k++) s2 += expf(wk0[k] - m2);
        float lse0 = m2 + logf(s2);
        int kp0 = 4 * (t & 7) + (t >> 3);   // blocked layout
        g_a0b[t] = (wk0[kp0] - lse0) * LOG2E;
    }
}

// ---------------------------------------------------------------------------
// Main: 128 threads (4 warps) per CTA, 8 samples per CTA (2 per warp).
// Double-buffered cp.async pipeline: step m+1's L tile (8 samples x 4KB) and
// W slice (4KB) stream into smem while step m computes from the other buffer.
// Compute core identical to round 4 (blocked lane layout, one-pass stable
// logsumexp in log2 domain), but all data comes from smem (LDS.128).
//   buffer layout (float4 units): [0..2047] = L (sample s at s*256),
//                                 [2048..2303] = W slice. 2304 f4 = 36 KB.
// ---------------------------------------------------------------------------
__global__ void __launch_bounds__(128)
tt_main_kernel(const float* __restrict__ L, float* __restrict__ out) {
    extern __shared__ float4 sbuf[];   // 2 * 2304 float4 = 72 KB
    const int tid  = threadIdx.x;
    const int wid  = tid >> 5;
    const int lane = tid & 31;
    const int rsub = lane >> 3;
    const int srcb = lane & 24;
    const int n0   = blockIdx.x * 8;     // first sample of this CTA
    const int sA   = 2 * wid;
    const int sB   = 2 * wid + 1;

    const float4* Lc = (const float4*)L + (size_t)n0 * 8192;
    const float4* W4 = (const float4*)g_wl2;

    unsigned int sb = (unsigned int)__cvta_generic_to_shared(sbuf);

    // Prologue: prefetch step 0 into buffer 0.
    {
#pragma unroll
        for (int j = 0; j < 16; j++) {
            int i = j * 128 + tid;                         // 0..2047 (L part)
            cpa16(sb + (unsigned int)i * 16u, Lc + ((i >> 8) * 8192 + (i & 255)));
        }
#pragma unroll
        for (int j = 0; j < 2; j++) {
            int f = j * 128 + tid;                         // 0..255 (W part)
            cpa16(sb + (unsigned int)(2048 + f) * 16u, W4 + f);
        }
        CP_COMMIT();
    }

    float bA = g_a0b[lane];   // log2 domain, blocked layout
    float bB = bA;

#pragma unroll 1
    for (int m = 0; m < 32; m++) {
        // Prefetch step m+1 into the other buffer (skipped on last step;
        // the empty commit keeps wait_group counting consistent).
        if (m + 1 < 32) {
            unsigned int db = sb + (unsigned int)((m + 1) & 1) * (2304u * 16u);
            int moff = (m + 1) * 256;
#pragma unroll
            for (int j = 0; j < 16; j++) {
                int i = j * 128 + tid;
                cpa16(db + (unsigned int)i * 16u,
                      Lc + ((i >> 8) * 8192 + moff + (i & 255)));
            }
#pragma unroll
            for (int j = 0; j < 2; j++) {
                int f = j * 128 + tid;
                cpa16(db + (unsigned int)(2048 + f) * 16u, W4 + (moff + f));
            }
        }
        CP_COMMIT();
        CP_WAIT1();          // current step's buffer complete (next may fly)
        __syncthreads();

        const float4* bufL = sbuf + (m & 1) * 2304;
        const float4* bufW = bufL + 2048;

        const float refA = __shfl_sync(FULL, bA, 0);
        const float refB = __shfl_sync(FULL, bB, 0);

        float4 accA = make_float4(0.f, 0.f, 0.f, 0.f);
        float4 accB = make_float4(0.f, 0.f, 0.f, 0.f);

#pragma unroll
        for (int blk = 0; blk < 8; blk++) {
            float4 w4  = bufW[blk * 32 + lane];
            float4 l4A = bufL[sA * 256 + blk * 32 + lane];
            float4 l4B = bufL[sB * 256 + blk * 32 + lane];
            float pA = ex2f(__shfl_sync(FULL, bA, srcb | blk) - refA);
            float pB = ex2f(__shfl_sync(FULL, bB, srcb | blk) - refB);

            accA.x = fmaf(pA, ex2f(fmaf(l4A.x, LOG2E, w4.x)), accA.x);
            accA.y = fmaf(pA, ex2f(fmaf(l4A.y, LOG2E, w4.y)), accA.y);
            accA.z = fmaf(pA, ex2f(fmaf(l4A.z, LOG2E, w4.z)), accA.z);
            accA.w = fmaf(pA, ex2f(fmaf(l4A.w, LOG2E, w4.w)), accA.w);
            accB.x = fmaf(pB, ex2f(fmaf(l4B.x, LOG2E, w4.x)), accB.x);
            accB.y = fmaf(pB, ex2f(fmaf(l4B.y, LOG2E, w4.y)), accB.y);
            accB.z = fmaf(pB, ex2f(fmaf(l4B.z, LOG2E, w4.z)), accB.z);
            accB.w = fmaf(pB, ex2f(fmaf(l4B.w, LOG2E, w4.w)), accB.w);
        }

        // Sum over the 4 row-residue lanes sharing each k' group.
#pragma unroll
        for (int off = 8; off <= 16; off <<= 1) {
            accA.x += __shfl_xor_sync(FULL, accA.x, off);
            accA.y += __shfl_xor_sync(FULL, accA.y, off);
            accA.z += __shfl_xor_sync(FULL, accA.z, off);
            accA.w += __shfl_xor_sync(FULL, accA.w, off);
            accB.x += __shfl_xor_sync(FULL, accB.x, off);
            accB.y += __shfl_xor_sync(FULL, accB.y, off);
            accB.z += __shfl_xor_sync(FULL, accB.z, off);
            accB.w += __shfl_xor_sync(FULL, accB.w, off);
        }

        // Stay in blocked layout: this lane keeps component rsub.
        float vA = (rsub & 2) ? ((rsub & 1) ? accA.w : accA.z)
                              : ((rsub & 1) ? accA.y : accA.x);
        float vB = (rsub & 2) ? ((rsub & 1) ? accB.w : accB.z)
                              : ((rsub & 1) ? accB.y : accB.x);

        bA = lg2f(vA) + refA;
        bB = lg2f(vB) + refB;

        __syncthreads();   // all reads of this buffer done before it refills
    }

    // Final logsumexp across lanes (layout is a permutation — invariant).
    float mA = bA, mB = bB;
#pragma unroll
    for (int off = 16; off; off >>= 1) {
        mA = fmaxf(mA, __shfl_xor_sync(FULL, mA, off));
        mB = fmaxf(mB, __shfl_xor_sync(FULL, mB, off));
    }
    float eA = ex2f(bA - mA);
    float eB = ex2f(bB - mB);
#pragma unroll
    for (int off = 16; off; off >>= 1) {
        eA += __shfl_xor_sync(FULL, eA, off);
        eB += __shfl_xor_sync(FULL, eB, off);
    }
    if (lane == 0) {
        out[n0 + sA] = (mA + lg2f(eA)) * LN2;
        out[n0 + sB] = (mB + lg2f(eB)) * LN2;
    }
}

// ---------------------------------------------------------------------------
// Launch contract
// ---------------------------------------------------------------------------
extern "C" void kernel_launch(void* const* d_in, const int* in_sizes, int n_in,
                              void* d_out, int out_size) {
    const float* L   = (const float*)d_in[0];   // [8192, 32, 32, 32]
    const float* wk0 = (const float*)d_in[1];   // [1, 32]
    const float* W   = (const float*)d_in[2];   // [32, 32, 32]
    float* out = (float*)d_out;                 // [8192]

    (void)in_sizes; (void)n_in; (void)out_size;

    cudaFuncSetAttribute(tt_main_kernel,
                         cudaFuncAttributeMaxDynamicSharedMemorySize, 73728);

    tt_prep_kernel<<<1, 1024>>>(W, wk0);
    // 8192 samples / 8 per CTA = 1024 CTAs; 3 CTAs/SM (smem-limited)
    tt_main_kernel<<<1024, 128, 73728>>>(L, out);
}